// round 14
// baseline (speedup 1.0000x reference)
#include <cuda_runtime.h>
#include <cuda_bf16.h>
#include <cstdint>

#define T_STEPS 4
#define BN      16384            // B*N = 32*512
#define DIMN    512
#define FLAG_CAP (1 << 22)

// ---------------- scratch (device globals; no allocs allowed) ----------------
__device__ __align__(16) signed char g_S[(size_t)T_STEPS * BN * DIMN];  // spikes s8 (32MB)
__device__ __align__(16) uint16_t    g_M[(size_t)T_STEPS * BN * 32];    // bit-packed spikes (4MB)
__device__ __align__(16) signed char g_Wl[2 * DIMN * DIMN];             // 2 base-256 limbs of W*2^16
__device__ __align__(16) int g_na[T_STEPS * BN];                        // active count per (t,row)
__device__ int g_nflag;
__device__ uint32_t g_flags[FLAG_CAP];

// ---------------- K1: LIF1 (bit-exact) + masks + counts + W limb split (merged) ----------------
#define LIF1_BLOCKS  (BN * 32 / 256)          // 2048
#define SPLIT_BLOCKS ((DIMN * DIMN) / 256)    // 1024

__global__ void k_prep(const float* __restrict__ in, const float* __restrict__ W) {
    int bid = blockIdx.x, tid = threadIdx.x;
    if (bid >= LIF1_BLOCKS) {
        // ---- W limb split + counter reset ----
        int i = (bid - LIF1_BLOCKS) * 256 + tid;
        if (i == 0) g_nflag = 0;
        int v = (int)llrintf(W[i] * 65536.0f);    // |W|<0.45 -> |v| < 29500 (safe)
        int d0 = ((v + 128) & 255) - 128;         // balanced digit in [-128,127]
        int d1 = (v - d0) >> 8;                   // exact, |d1| <= 116
        g_Wl[i]               = (signed char)d0;
        g_Wl[DIMN * DIMN + i] = (signed char)d1;
        return;
    }
    // ---- LIF1: one warp per bn row, lane covers 16 consecutive d ----
    int gt = bid * 256 + tid;
    int bn = gt >> 5, lane = gt & 31;
    int d0 = lane * 16;
    float v[16];
#pragma unroll
    for (int j = 0; j < 16; ++j) v[j] = 0.f;
#pragma unroll
    for (int t = 0; t < T_STEPS; ++t) {
        const float4* xp = reinterpret_cast<const float4*>(
            in + ((size_t)(t * BN + bn)) * 1024 + 512 + d0);
        uint32_t pk[4];
        uint32_t mbits = 0;
        int cnt = 0;
#pragma unroll
        for (int q = 0; q < 4; ++q) {
            float4 x = xp[q];
            float xv[4] = {x.x, x.y, x.z, x.w};
            uint32_t b = 0;
#pragma unroll
            for (int j = 0; j < 4; ++j) {
                int jj = q * 4 + j;
                v[jj] = v[jj] * 0.5f + xv[j];      // *0.5 exact -> bit-identical to ref
                int s = (v[jj] >= 1.0f) ? 1 : 0;
                v[jj] = s ? 0.f : v[jj];
                b |= (uint32_t)s << (8 * j);
                mbits |= (uint32_t)s << jj;
                cnt += s;
            }
            pk[q] = b;
        }
        *reinterpret_cast<uint4*>(g_S + ((size_t)(t * BN + bn)) * 512 + d0) =
            make_uint4(pk[0], pk[1], pk[2], pk[3]);
        g_M[((size_t)(t * BN + bn)) * 32 + lane] = (uint16_t)mbits;
#pragma unroll
        for (int off = 16; off; off >>= 1)
            cnt += __shfl_xor_sync(0xFFFFFFFF, cnt, off);
        if (lane == 0) g_na[t * BN + bn] = cnt;
    }
}

// ---------------- asm helpers ----------------
__device__ __forceinline__ uint32_t smem_u32(const void* p) {
    uint32_t r;
    asm("{ .reg .u64 t; cvta.to.shared.u64 t, %1; cvt.u32.u64 %0, t; }" : "=r"(r) : "l"(p));
    return r;
}
__device__ __forceinline__ void cp16(uint32_t saddr, const void* g) {
    asm volatile("cp.async.cg.shared.global [%0], [%1], 16;" :: "r"(saddr), "l"(g) : "memory");
}
#define CP_COMMIT() asm volatile("cp.async.commit_group;" ::: "memory")
#define CP_WAIT(n)  asm volatile("cp.async.wait_group %0;" :: "n"(n) : "memory")

__device__ __forceinline__ void ldm_x4(uint32_t* a, uint32_t addr) {
    asm volatile("ldmatrix.sync.aligned.m8n8.x4.shared.b16 {%0,%1,%2,%3}, [%4];"
                 : "=r"(a[0]), "=r"(a[1]), "=r"(a[2]), "=r"(a[3]) : "r"(addr));
}
__device__ __forceinline__ void mma_s8(int* c, const uint32_t* a, uint32_t b0, uint32_t b1) {
    asm volatile(
        "mma.sync.aligned.m16n8k32.row.col.s32.s8.s8.s32 "
        "{%0,%1,%2,%3}, {%4,%5,%6,%7}, {%8,%9}, {%0,%1,%2,%3};"
        : "+r"(c[0]), "+r"(c[1]), "+r"(c[2]), "+r"(c[3])
        : "r"(a[0]), "r"(a[1]), "r"(a[2]), "r"(a[3]), "r"(b0), "r"(b1));
}

// ---------------- K2: 2-limb exact GEMM + LIF2 + gated multiply + tie flagging ----------------
// CTA tile 128(bn) x 32(e), 256 threads, 2 CTAs/SM; K_CHUNK=128.
#define M_TILE   128
#define N_TILE   32
#define K_CHUNK  128
#define B_LIMB_B (N_TILE * DIMN)              // 16384 per limb
#define B_BYTES  (2 * B_LIMB_B)               // 32768 (resident W limbs)
#define A_STAGE  (M_TILE * K_CHUNK)           // 16384
#define IN_OFF   (B_BYTES + 2 * A_STAGE)      // 65536: in-tile [128 x 32] f32 (16KB)
#define NA_OFF   (IN_OFF + M_TILE * N_TILE * 4)  // 81920: na[128]
#define SMEM_TOTAL (NA_OFF + 512)             // 82432

__device__ __forceinline__ void load_A(uint32_t sA, const signed char* __restrict__ gA, int tid) {
#pragma unroll
    for (int i = 0; i < 4; ++i) {
        int lin = tid + i * 256;             // 1024 x 16B = 16KB
        int row = lin >> 3, ch = lin & 7;
        cp16(sA + (uint32_t)(row * 128 + ((ch ^ (row & 7)) * 16)),
             gA + (size_t)row * 512 + ch * 16);
    }
}

__global__ __launch_bounds__(256, 2)
void k_gemm_lif2(const float* __restrict__ in, const float* __restrict__ bvec,
                 float* __restrict__ out) {
    extern __shared__ char smem[];
    const uint32_t sB = smem_u32(smem);
    const uint32_t sAb = sB + B_BYTES;
    const int tid = threadIdx.x, wid = tid >> 5, lane = tid & 31;
    const int wm = wid & 3, wn = wid >> 2;     // wn in {0,1}
    const int bn0 = blockIdx.x * M_TILE;
    const int et0 = blockIdx.y * N_TILE;

    // ---- resident B: 2 limbs x [32 e-rows x 512 k-bytes], swizzled ----
#pragma unroll
    for (int i = 0; i < 8; ++i) {
        int lin = tid + i * 256;
        int limb = lin >> 10, rem = lin & 1023;
        int n = rem >> 5, kc = rem & 31;
        cp16(sB + (uint32_t)(limb * B_LIMB_B + n * 512 + ((kc ^ (n & 7)) * 16)),
             g_Wl + (size_t)limb * (DIMN * DIMN) + (size_t)(et0 + n) * 512 + kc * 16);
    }
    CP_COMMIT();

    // prologue: A chunks 0,1 (t=0)
    load_A(sAb,           g_S + ((size_t)bn0) * 512 + 0 * K_CHUNK, tid);
    CP_COMMIT();
    load_A(sAb + A_STAGE, g_S + ((size_t)bn0) * 512 + 1 * K_CHUNK, tid);
    CP_COMMIT();

    float bb[2][2];
#pragma unroll
    for (int ng = 0; ng < 2; ++ng)
#pragma unroll
        for (int q = 0; q < 2; ++q)
            bb[ng][q] = bvec[et0 + wn * 16 + ng * 8 + 2 * (lane & 3) + q];

    const int lrow = lane & 15, lch = lane >> 4;
    const float* inS = (const float*)(smem + IN_OFF);
    const int*   naS = (const int*)(smem + NA_OFF);

    float v[2][2][4];
#pragma unroll
    for (int i = 0; i < 2; ++i)
#pragma unroll
        for (int ng = 0; ng < 2; ++ng)
#pragma unroll
            for (int e = 0; e < 4; ++e) v[i][ng][e] = 0.f;

    unsigned fl = 0;

#pragma unroll 1
    for (int t = 0; t < T_STEPS; ++t) {
        int acc[2][2][2][4];
#pragma unroll
        for (int l = 0; l < 2; ++l)
#pragma unroll
            for (int i = 0; i < 2; ++i)
#pragma unroll
                for (int ng = 0; ng < 2; ++ng)
#pragma unroll
                    for (int e = 0; e < 4; ++e) acc[l][i][ng][e] = 0;

#pragma unroll 1
        for (int c = 0; c < 4; ++c) {
            const int gc = t * 4 + c;
            CP_WAIT(1);
            __syncthreads();
            const uint32_t sA = sAb + (uint32_t)((gc & 1) * A_STAGE);

#pragma unroll
            for (int ks = 0; ks < 4; ++ks) {
                uint32_t a[2][4];
#pragma unroll
                for (int i = 0; i < 2; ++i) {
                    int row = wm * 32 + i * 16 + lrow;
                    int ch = ks * 2 + lch;
                    ldm_x4(a[i], sA + (uint32_t)(row * 128 + ((ch ^ (row & 7)) * 16)));
                }
#pragma unroll
                for (int l = 0; l < 2; ++l) {
                    uint32_t bf[4];
                    int n = wn * 16 + lrow;
                    int kc = c * 8 + ks * 2 + lch;
                    ldm_x4(bf, sB + (uint32_t)(l * B_LIMB_B + n * 512 + ((kc ^ (n & 7)) * 16)));
#pragma unroll
                    for (int i = 0; i < 2; ++i) {
                        mma_s8(acc[l][i][0], a[i], bf[0], bf[2]);
                        mma_s8(acc[l][i][1], a[i], bf[1], bf[3]);
                    }
                }
            }
            __syncthreads();

            if (c == 0) {
                // prefetch this t's outputs-tile + na row into smem
                const float* gin = in + ((size_t)(t * BN + bn0)) * 1024 + et0;
#pragma unroll
                for (int i2 = 0; i2 < 4; ++i2) {
                    int lin = i2 * 256 + tid;
                    int r = lin >> 3, cg = lin & 7;
                    cp16(sB + (uint32_t)(IN_OFF + r * 128 + cg * 16),
                         gin + (size_t)r * 1024 + cg * 4);
                }
                if (tid < 32)
                    cp16(sB + (uint32_t)(NA_OFF + tid * 16), g_na + t * BN + bn0 + tid * 4);
            }
            int next = gc + 2;
            if (next < 16) {
                int tn = next >> 2, cn = next & 3;
                load_A(sAb + (uint32_t)((gc & 1) * A_STAGE),
                       g_S + ((size_t)(tn * BN + bn0)) * 512 + cn * K_CHUNK, tid);
            }
            CP_COMMIT();
        }

        // ---- epilogue: exact reconstruction + bias + LIF2 + flag + gated multiply ----
#pragma unroll
        for (int i = 0; i < 2; ++i) {
#pragma unroll
            for (int h = 0; h < 2; ++h) {
                int rowl = wm * 32 + i * 16 + (lane >> 2) + h * 8;
                // hard bound on |v - v_ref|: quant (na*2^-17 half-ulp, x2 membrane) + chain
                float na = (float)naS[rowl];
                float tau = fmaf(na, 1.52587890625e-05f, 4e-4f);
#pragma unroll
                for (int ng = 0; ng < 2; ++ng) {
                    int coll = wn * 16 + ng * 8 + 2 * (lane & 3);
                    float s[2];
#pragma unroll
                    for (int q = 0; q < 2; ++q) {
                        int e = 2 * h + q;
                        float y = fmaf((float)acc[1][i][ng][e], 256.0f,
                                       (float)acc[0][i][ng][e])
                                  * 1.52587890625e-05f;                // * 2^-16, all exact
                        float g = y + bb[ng][q];
                        float vv = v[i][ng][e] * 0.5f + g;
                        float sp = (vv >= 1.0f) ? 1.0f : 0.0f;
                        v[i][ng][e] = vv * (1.0f - sp);
                        s[q] = sp;
                        if (fabsf(vv - 1.0f) < tau)
                            fl |= 1u << (i * 8 + ng * 4 + h * 2 + q);
                    }
                    const float2 o = *reinterpret_cast<const float2*>(
                        inS + rowl * N_TILE + coll);
                    size_t grow = (size_t)(t * BN) + bn0 + rowl;
                    float2 r;
                    r.x = o.x * s[0];
                    r.y = o.y * s[1];
                    *reinterpret_cast<float2*>(out + grow * 512 + et0 + coll) = r;
                }
            }
        }
    }

    if (fl) {
#pragma unroll
        for (int i = 0; i < 2; ++i)
#pragma unroll
            for (int ng = 0; ng < 2; ++ng)
#pragma unroll
                for (int h = 0; h < 2; ++h)
#pragma unroll
                    for (int q = 0; q < 2; ++q)
                        if (fl & (1u << (i * 8 + ng * 4 + h * 2 + q))) {
                            int row = bn0 + wm * 32 + i * 16 + (lane >> 2) + h * 8;
                            int col = et0 + wn * 16 + ng * 8 + 2 * (lane & 3) + q;
                            int idx = atomicAdd(&g_nflag, 1);
                            if (idx < FLAG_CAP)
                                g_flags[idx] = (uint32_t)(row * 512 + col);
                        }
    }
}

// ---------------- K3: thread-per-flag fixup with bit-packed masks ----------------
// Masks (4 x 64B) loaded up-front; W row streamed as float4 with MLP; four
// independent exact ascending-d predicated add-chains (one per t).
__global__ void k_fixup(const float* __restrict__ in, const float* __restrict__ W,
                        const float* __restrict__ bvec, float* __restrict__ out) {
    int n = g_nflag;
    if (n > FLAG_CAP) n = FLAG_CAP;
    for (int idx = blockIdx.x * blockDim.x + threadIdx.x; idx < n;
         idx += gridDim.x * blockDim.x) {
        uint32_t key = g_flags[idx];
        int bn = (int)(key >> 9), e = (int)(key & 511);

        // load all 4 t-masks (16 uint4, independent -> one round-trip)
        uint32_t mw[T_STEPS][16];
#pragma unroll
        for (int t = 0; t < T_STEPS; ++t) {
            const uint4* mp = reinterpret_cast<const uint4*>(
                g_M + ((size_t)(t * BN + bn)) * 32);
#pragma unroll
            for (int u = 0; u < 4; ++u) {
                uint4 m = mp[u];
                mw[t][u * 4 + 0] = m.x;
                mw[t][u * 4 + 1] = m.y;
                mw[t][u * 4 + 2] = m.z;
                mw[t][u * 4 + 3] = m.w;
            }
        }

        const float4* w4 = reinterpret_cast<const float4*>(W + (size_t)e * 512);
        float acc[T_STEPS] = {0.f, 0.f, 0.f, 0.f};

#pragma unroll 4
        for (int c = 0; c < 32; ++c) {           // 16 d per chunk
            float4 wa = w4[c * 4 + 0], wb = w4[c * 4 + 1];
            float4 wc = w4[c * 4 + 2], wd = w4[c * 4 + 3];
            float wv[16] = {wa.x, wa.y, wa.z, wa.w, wb.x, wb.y, wb.z, wb.w,
                            wc.x, wc.y, wc.z, wc.w, wd.x, wd.y, wd.z, wd.w};
#pragma unroll
            for (int t = 0; t < T_STEPS; ++t) {
                uint32_t m = mw[t][c >> 1] >> ((c & 1) * 16);
#pragma unroll
                for (int j = 0; j < 16; ++j)
                    acc[t] = ((m >> j) & 1u) ? (acc[t] + wv[j]) : acc[t];  // exact chain
            }
        }

        float bias = bvec[e];
        float v = 0.f;
#pragma unroll
        for (int t = 0; t < T_STEPS; ++t) {
            float g = acc[t] + bias;
            float vv = v * 0.5f + g;
            float s = (vv >= 1.0f) ? 1.0f : 0.0f;
            v = vv * (1.0f - s);
            size_t grow = (size_t)(t * BN) + bn;
            out[grow * 512 + e] = in[grow * 1024 + e] * s;
        }
    }
}

// ---------------- launcher ----------------
extern "C" void kernel_launch(void* const* d_in, const int* in_sizes, int n_in,
                              void* d_out, int out_size) {
    const float* inputs = (const float*)d_in[0];   // [4,32,512,1024]
    const float* W      = (const float*)d_in[1];   // [512,512]
    const float* b      = (const float*)d_in[2];   // [512]
    float* out          = (float*)d_out;           // [4,32,512,512]

    cudaFuncSetAttribute(k_gemm_lif2, cudaFuncAttributeMaxDynamicSharedMemorySize, SMEM_TOTAL);

    k_prep<<<LIF1_BLOCKS + SPLIT_BLOCKS, 256>>>(inputs, W);
    k_gemm_lif2<<<dim3(BN / M_TILE, DIMN / N_TILE), 256, SMEM_TOTAL>>>(inputs, b, out);
    k_fixup<<<1024, 256>>>(inputs, W, b, out);
}

// round 15
// speedup vs baseline: 1.6181x; 1.6181x over previous
#include <cuda_runtime.h>
#include <cuda_bf16.h>
#include <cstdint>

#define T_STEPS 4
#define BN      16384            // B*N = 32*512
#define DIMN    512
#define FLAG_CAP (1 << 22)

// ---------------- scratch (device globals; no allocs allowed) ----------------
__device__ __align__(16) signed char g_S[(size_t)T_STEPS * BN * DIMN];  // spikes s8 (32MB)
__device__ __align__(16) uint32_t    g_M32[(size_t)T_STEPS * BN * 16];  // packed spike masks (4MB)
__device__ __align__(16) signed char g_Wl[2 * DIMN * DIMN];             // 2 base-256 limbs of W*2^16
__device__ __align__(16) int g_na[T_STEPS * BN];                        // active count per (t,row)
__device__ int g_nflag;
__device__ uint32_t g_flags[FLAG_CAP];

// ---------------- K1: LIF1 (bit-exact) + packed masks + counts + W limb split ----------------
#define LIF1_BLOCKS  (BN * 32 / 256)          // 2048
#define SPLIT_BLOCKS ((DIMN * DIMN) / 256)    // 1024

__global__ void k_prep(const float* __restrict__ in, const float* __restrict__ W) {
    int bid = blockIdx.x, tid = threadIdx.x;
    if (bid >= LIF1_BLOCKS) {
        // ---- W limb split + counter reset ----
        int i = (bid - LIF1_BLOCKS) * 256 + tid;
        if (i == 0) g_nflag = 0;
        int v = (int)llrintf(W[i] * 65536.0f);    // |W|<0.45 -> |v| < 29500 (safe)
        int d0 = ((v + 128) & 255) - 128;         // balanced digit in [-128,127]
        int d1 = (v - d0) >> 8;                   // exact, |d1| <= 116
        g_Wl[i]               = (signed char)d0;
        g_Wl[DIMN * DIMN + i] = (signed char)d1;
        return;
    }
    // ---- LIF1: one warp per bn row, lane covers 16 consecutive d ----
    int gt = bid * 256 + tid;
    int bn = gt >> 5, lane = gt & 31;
    int d0 = lane * 16;
    float v[16];
#pragma unroll
    for (int j = 0; j < 16; ++j) v[j] = 0.f;
#pragma unroll
    for (int t = 0; t < T_STEPS; ++t) {
        const float4* xp = reinterpret_cast<const float4*>(
            in + ((size_t)(t * BN + bn)) * 1024 + 512 + d0);
        uint32_t pk[4];
        uint32_t mbits = 0;
        int cnt = 0;
#pragma unroll
        for (int q = 0; q < 4; ++q) {
            float4 x = xp[q];
            float xv[4] = {x.x, x.y, x.z, x.w};
            uint32_t b = 0;
#pragma unroll
            for (int j = 0; j < 4; ++j) {
                int jj = q * 4 + j;
                v[jj] = v[jj] * 0.5f + xv[j];      // *0.5 exact -> bit-identical to ref
                int s = (v[jj] >= 1.0f) ? 1 : 0;
                v[jj] = s ? 0.f : v[jj];
                b |= (uint32_t)s << (8 * j);
                mbits |= (uint32_t)s << jj;
                cnt += s;
            }
            pk[q] = b;
        }
        *reinterpret_cast<uint4*>(g_S + ((size_t)(t * BN + bn)) * 512 + d0) =
            make_uint4(pk[0], pk[1], pk[2], pk[3]);
        // pack pairs of lanes into uint32 (bit k of word w <-> d = 32*w + k)
        uint32_t hi = __shfl_down_sync(0xFFFFFFFF, mbits, 1);
        if ((lane & 1) == 0)
            g_M32[((size_t)(t * BN + bn)) * 16 + (lane >> 1)] = mbits | (hi << 16);
#pragma unroll
        for (int off = 16; off; off >>= 1)
            cnt += __shfl_xor_sync(0xFFFFFFFF, cnt, off);
        if (lane == 0) g_na[t * BN + bn] = cnt;
    }
}

// ---------------- asm helpers ----------------
__device__ __forceinline__ uint32_t smem_u32(const void* p) {
    uint32_t r;
    asm("{ .reg .u64 t; cvta.to.shared.u64 t, %1; cvt.u32.u64 %0, t; }" : "=r"(r) : "l"(p));
    return r;
}
__device__ __forceinline__ void cp16(uint32_t saddr, const void* g) {
    asm volatile("cp.async.cg.shared.global [%0], [%1], 16;" :: "r"(saddr), "l"(g) : "memory");
}
#define CP_COMMIT() asm volatile("cp.async.commit_group;" ::: "memory")
#define CP_WAIT(n)  asm volatile("cp.async.wait_group %0;" :: "n"(n) : "memory")

__device__ __forceinline__ void ldm_x4(uint32_t* a, uint32_t addr) {
    asm volatile("ldmatrix.sync.aligned.m8n8.x4.shared.b16 {%0,%1,%2,%3}, [%4];"
                 : "=r"(a[0]), "=r"(a[1]), "=r"(a[2]), "=r"(a[3]) : "r"(addr));
}
__device__ __forceinline__ void mma_s8(int* c, const uint32_t* a, uint32_t b0, uint32_t b1) {
    asm volatile(
        "mma.sync.aligned.m16n8k32.row.col.s32.s8.s8.s32 "
        "{%0,%1,%2,%3}, {%4,%5,%6,%7}, {%8,%9}, {%0,%1,%2,%3};"
        : "+r"(c[0]), "+r"(c[1]), "+r"(c[2]), "+r"(c[3])
        : "r"(a[0]), "r"(a[1]), "r"(a[2]), "r"(a[3]), "r"(b0), "r"(b1));
}

// ---------------- K2: 2-limb exact GEMM + LIF2 + gated multiply + tie flagging ----------------
// CTA tile 128(bn) x 32(e), 256 threads, 2 CTAs/SM; K_CHUNK=128.
#define M_TILE   128
#define N_TILE   32
#define K_CHUNK  128
#define B_LIMB_B (N_TILE * DIMN)              // 16384 per limb
#define B_BYTES  (2 * B_LIMB_B)               // 32768 (resident W limbs)
#define A_STAGE  (M_TILE * K_CHUNK)           // 16384
#define IN_OFF   (B_BYTES + 2 * A_STAGE)      // 65536: in-tile [128 x 32] f32 (16KB)
#define NA_OFF   (IN_OFF + M_TILE * N_TILE * 4)  // 81920: na[128]
#define SMEM_TOTAL (NA_OFF + 512)             // 82432

__device__ __forceinline__ void load_A(uint32_t sA, const signed char* __restrict__ gA, int tid) {
#pragma unroll
    for (int i = 0; i < 4; ++i) {
        int lin = tid + i * 256;             // 1024 x 16B = 16KB
        int row = lin >> 3, ch = lin & 7;
        cp16(sA + (uint32_t)(row * 128 + ((ch ^ (row & 7)) * 16)),
             gA + (size_t)row * 512 + ch * 16);
    }
}

__global__ __launch_bounds__(256, 2)
void k_gemm_lif2(const float* __restrict__ in, const float* __restrict__ bvec,
                 float* __restrict__ out) {
    extern __shared__ char smem[];
    const uint32_t sB = smem_u32(smem);
    const uint32_t sAb = sB + B_BYTES;
    const int tid = threadIdx.x, wid = tid >> 5, lane = tid & 31;
    const int wm = wid & 3, wn = wid >> 2;     // wn in {0,1}
    const int bn0 = blockIdx.x * M_TILE;
    const int et0 = blockIdx.y * N_TILE;

    // ---- resident B: 2 limbs x [32 e-rows x 512 k-bytes], swizzled ----
#pragma unroll
    for (int i = 0; i < 8; ++i) {
        int lin = tid + i * 256;
        int limb = lin >> 10, rem = lin & 1023;
        int n = rem >> 5, kc = rem & 31;
        cp16(sB + (uint32_t)(limb * B_LIMB_B + n * 512 + ((kc ^ (n & 7)) * 16)),
             g_Wl + (size_t)limb * (DIMN * DIMN) + (size_t)(et0 + n) * 512 + kc * 16);
    }
    CP_COMMIT();

    // prologue: A chunks 0,1 (t=0)
    load_A(sAb,           g_S + ((size_t)bn0) * 512 + 0 * K_CHUNK, tid);
    CP_COMMIT();
    load_A(sAb + A_STAGE, g_S + ((size_t)bn0) * 512 + 1 * K_CHUNK, tid);
    CP_COMMIT();

    float bb[2][2];
#pragma unroll
    for (int ng = 0; ng < 2; ++ng)
#pragma unroll
        for (int q = 0; q < 2; ++q)
            bb[ng][q] = bvec[et0 + wn * 16 + ng * 8 + 2 * (lane & 3) + q];

    const int lrow = lane & 15, lch = lane >> 4;
    const float* inS = (const float*)(smem + IN_OFF);
    const int*   naS = (const int*)(smem + NA_OFF);

    float v[2][2][4];
#pragma unroll
    for (int i = 0; i < 2; ++i)
#pragma unroll
        for (int ng = 0; ng < 2; ++ng)
#pragma unroll
            for (int e = 0; e < 4; ++e) v[i][ng][e] = 0.f;

    unsigned fl = 0;

#pragma unroll 1
    for (int t = 0; t < T_STEPS; ++t) {
        int acc[2][2][2][4];
#pragma unroll
        for (int l = 0; l < 2; ++l)
#pragma unroll
            for (int i = 0; i < 2; ++i)
#pragma unroll
                for (int ng = 0; ng < 2; ++ng)
#pragma unroll
                    for (int e = 0; e < 4; ++e) acc[l][i][ng][e] = 0;

#pragma unroll 1
        for (int c = 0; c < 4; ++c) {
            const int gc = t * 4 + c;
            CP_WAIT(1);
            __syncthreads();
            const uint32_t sA = sAb + (uint32_t)((gc & 1) * A_STAGE);

#pragma unroll
            for (int ks = 0; ks < 4; ++ks) {
                uint32_t a[2][4];
#pragma unroll
                for (int i = 0; i < 2; ++i) {
                    int row = wm * 32 + i * 16 + lrow;
                    int ch = ks * 2 + lch;
                    ldm_x4(a[i], sA + (uint32_t)(row * 128 + ((ch ^ (row & 7)) * 16)));
                }
#pragma unroll
                for (int l = 0; l < 2; ++l) {
                    uint32_t bf[4];
                    int n = wn * 16 + lrow;
                    int kc = c * 8 + ks * 2 + lch;
                    ldm_x4(bf, sB + (uint32_t)(l * B_LIMB_B + n * 512 + ((kc ^ (n & 7)) * 16)));
#pragma unroll
                    for (int i = 0; i < 2; ++i) {
                        mma_s8(acc[l][i][0], a[i], bf[0], bf[2]);
                        mma_s8(acc[l][i][1], a[i], bf[1], bf[3]);
                    }
                }
            }
            __syncthreads();

            if (c == 0) {
                // prefetch this t's outputs-tile + na row into smem
                const float* gin = in + ((size_t)(t * BN + bn0)) * 1024 + et0;
#pragma unroll
                for (int i2 = 0; i2 < 4; ++i2) {
                    int lin = i2 * 256 + tid;
                    int r = lin >> 3, cg = lin & 7;
                    cp16(sB + (uint32_t)(IN_OFF + r * 128 + cg * 16),
                         gin + (size_t)r * 1024 + cg * 4);
                }
                if (tid < 32)
                    cp16(sB + (uint32_t)(NA_OFF + tid * 16), g_na + t * BN + bn0 + tid * 4);
            }
            int next = gc + 2;
            if (next < 16) {
                int tn = next >> 2, cn = next & 3;
                load_A(sAb + (uint32_t)((gc & 1) * A_STAGE),
                       g_S + ((size_t)(tn * BN + bn0)) * 512 + cn * K_CHUNK, tid);
            }
            CP_COMMIT();
        }

        // ---- epilogue: exact reconstruction + bias + LIF2 + flag + gated multiply ----
#pragma unroll
        for (int i = 0; i < 2; ++i) {
#pragma unroll
            for (int h = 0; h < 2; ++h) {
                int rowl = wm * 32 + i * 16 + (lane >> 2) + h * 8;
                // hard bound on |v - v_ref|: quant (na*2^-17 half-ulp, x2 membrane) + chain
                float na = (float)naS[rowl];
                float tau = fmaf(na, 1.52587890625e-05f, 4e-4f);
#pragma unroll
                for (int ng = 0; ng < 2; ++ng) {
                    int coll = wn * 16 + ng * 8 + 2 * (lane & 3);
                    float s[2];
#pragma unroll
                    for (int q = 0; q < 2; ++q) {
                        int e = 2 * h + q;
                        float y = fmaf((float)acc[1][i][ng][e], 256.0f,
                                       (float)acc[0][i][ng][e])
                                  * 1.52587890625e-05f;                // * 2^-16, all exact
                        float g = y + bb[ng][q];
                        float vv = v[i][ng][e] * 0.5f + g;
                        float sp = (vv >= 1.0f) ? 1.0f : 0.0f;
                        v[i][ng][e] = vv * (1.0f - sp);
                        s[q] = sp;
                        if (fabsf(vv - 1.0f) < tau)
                            fl |= 1u << (i * 8 + ng * 4 + h * 2 + q);
                    }
                    const float2 o = *reinterpret_cast<const float2*>(
                        inS + rowl * N_TILE + coll);
                    size_t grow = (size_t)(t * BN) + bn0 + rowl;
                    float2 r;
                    r.x = o.x * s[0];
                    r.y = o.y * s[1];
                    *reinterpret_cast<float2*>(out + grow * 512 + et0 + coll) = r;
                }
            }
        }
    }

    if (fl) {
#pragma unroll
        for (int i = 0; i < 2; ++i)
#pragma unroll
            for (int ng = 0; ng < 2; ++ng)
#pragma unroll
                for (int h = 0; h < 2; ++h)
#pragma unroll
                    for (int q = 0; q < 2; ++q)
                        if (fl & (1u << (i * 8 + ng * 4 + h * 2 + q))) {
                            int row = bn0 + wm * 32 + i * 16 + (lane >> 2) + h * 8;
                            int col = et0 + wn * 16 + ng * 8 + 2 * (lane & 3) + q;
                            int idx = atomicAdd(&g_nflag, 1);
                            if (idx < FLAG_CAP)
                                g_flags[idx] = (uint32_t)(row * 512 + col);
                        }
    }
}

// ---------------- K3: thread-per-flag fixup (packed masks, spill-free) ----------------
// Per 128-d group: 4 uint4 mask loads + 32 float4 W loads (L2-hot, 1MB total).
// Four exact ascending-d predicated add-chains (one per t) -> bit-identical to reference.
__global__ __launch_bounds__(256)
void k_fixup(const float* __restrict__ in, const float* __restrict__ W,
             const float* __restrict__ bvec, float* __restrict__ out) {
    int n = g_nflag;
    if (n > FLAG_CAP) n = FLAG_CAP;
    for (int idx = blockIdx.x * blockDim.x + threadIdx.x; idx < n;
         idx += gridDim.x * blockDim.x) {
        uint32_t key = g_flags[idx];
        int bn = (int)(key >> 9), e = (int)(key & 511);
        const float4* w4 = reinterpret_cast<const float4*>(W + (size_t)e * 512);

        float acc0 = 0.f, acc1 = 0.f, acc2 = 0.f, acc3 = 0.f;
#pragma unroll 1
        for (int g = 0; g < 4; ++g) {             // 128 d per group
            uint4 m0 = reinterpret_cast<const uint4*>(g_M32 + ((size_t)(0 * BN + bn)) * 16)[g];
            uint4 m1 = reinterpret_cast<const uint4*>(g_M32 + ((size_t)(1 * BN + bn)) * 16)[g];
            uint4 m2 = reinterpret_cast<const uint4*>(g_M32 + ((size_t)(2 * BN + bn)) * 16)[g];
            uint4 m3 = reinterpret_cast<const uint4*>(g_M32 + ((size_t)(3 * BN + bn)) * 16)[g];
#pragma unroll
            for (int u = 0; u < 4; ++u) {         // 32 d per mask word
                uint32_t w0 = (&m0.x)[u], w1 = (&m1.x)[u];
                uint32_t w2 = (&m2.x)[u], w3 = (&m3.x)[u];
#pragma unroll
                for (int b = 0; b < 8; ++b) {     // 4 d per float4
                    float4 wv = w4[g * 32 + u * 8 + b];
                    const float wf[4] = {wv.x, wv.y, wv.z, wv.w};
#pragma unroll
                    for (int j = 0; j < 4; ++j) {
                        int bit = b * 4 + j;
                        acc0 = ((w0 >> bit) & 1u) ? (acc0 + wf[j]) : acc0;
                        acc1 = ((w1 >> bit) & 1u) ? (acc1 + wf[j]) : acc1;
                        acc2 = ((w2 >> bit) & 1u) ? (acc2 + wf[j]) : acc2;
                        acc3 = ((w3 >> bit) & 1u) ? (acc3 + wf[j]) : acc3;
                    }
                }
            }
        }

        float accs[T_STEPS] = {acc0, acc1, acc2, acc3};
        float bias = bvec[e];
        float v = 0.f;
#pragma unroll
        for (int t = 0; t < T_STEPS; ++t) {
            float g = accs[t] + bias;
            float vv = v * 0.5f + g;
            float s = (vv >= 1.0f) ? 1.0f : 0.0f;
            v = vv * (1.0f - s);
            size_t grow = (size_t)(t * BN) + bn;
            out[grow * 512 + e] = in[grow * 1024 + e] * s;
        }
    }
}

// ---------------- launcher ----------------
extern "C" void kernel_launch(void* const* d_in, const int* in_sizes, int n_in,
                              void* d_out, int out_size) {
    const float* inputs = (const float*)d_in[0];   // [4,32,512,1024]
    const float* W      = (const float*)d_in[1];   // [512,512]
    const float* b      = (const float*)d_in[2];   // [512]
    float* out          = (float*)d_out;           // [4,32,512,512]

    cudaFuncSetAttribute(k_gemm_lif2, cudaFuncAttributeMaxDynamicSharedMemorySize, SMEM_TOTAL);

    k_prep<<<LIF1_BLOCKS + SPLIT_BLOCKS, 256>>>(inputs, W);
    k_gemm_lif2<<<dim3(BN / M_TILE, DIMN / N_TILE), 256, SMEM_TOTAL>>>(inputs, b, out);
    k_fixup<<<2048, 256>>>(inputs, W, b, out);
}

// round 16
// speedup vs baseline: 1.6184x; 1.0002x over previous
#include <cuda_runtime.h>
#include <cuda_bf16.h>
#include <cstdint>

#define T_STEPS 4
#define BN      16384            // B*N = 32*512
#define DIMN    512
#define FLAG_CAP (1 << 22)

// ---------------- scratch (device globals; no allocs allowed) ----------------
__device__ __align__(16) signed char g_S[(size_t)T_STEPS * BN * DIMN];  // spikes s8 (32MB)
__device__ __align__(16) uint32_t    g_M32[(size_t)T_STEPS * BN * 16];  // packed spike masks (4MB)
__device__ __align__(16) signed char g_Wl[2 * DIMN * DIMN];             // 2 base-256 limbs of W*2^17
__device__ __align__(16) int g_na[T_STEPS * BN];                        // active count per (t,row)
__device__ __align__(16) int g_ovf[DIMN];                               // per-column quant overflow (0-init; set-only)
__device__ int g_nflag;
__device__ uint32_t g_flags[FLAG_CAP];

// ---------------- K1: LIF1 (bit-exact) + packed masks + counts + W limb split ----------------
#define LIF1_BLOCKS  (BN * 32 / 256)          // 2048
#define SPLIT_BLOCKS ((DIMN * DIMN) / 256)    // 1024

__global__ void k_prep(const float* __restrict__ in, const float* __restrict__ W) {
    int bid = blockIdx.x, tid = threadIdx.x;
    if (bid >= LIF1_BLOCKS) {
        // ---- W limb split (scale 2^17, clamped + per-column overflow flag) ----
        int i = (bid - LIF1_BLOCKS) * 256 + tid;
        if (i == 0) g_nflag = 0;
        int v = (int)llrintf(W[i] * 131072.0f);   // 2^17; |W|<0.249 -> |v| <= 32639
        if (v > 32639)  { v = 32639;  g_ovf[i >> 9] = 1; }
        if (v < -32639) { v = -32639; g_ovf[i >> 9] = 1; }
        int d0 = ((v + 128) & 255) - 128;         // balanced digit in [-128,127]
        int d1 = (v - d0) >> 8;                   // exact, |d1| <= 127
        g_Wl[i]               = (signed char)d0;
        g_Wl[DIMN * DIMN + i] = (signed char)d1;
        return;
    }
    // ---- LIF1: one warp per bn row, lane covers 16 consecutive d ----
    int gt = bid * 256 + tid;
    int bn = gt >> 5, lane = gt & 31;
    int d0 = lane * 16;
    float v[16];
#pragma unroll
    for (int j = 0; j < 16; ++j) v[j] = 0.f;
#pragma unroll
    for (int t = 0; t < T_STEPS; ++t) {
        const float4* xp = reinterpret_cast<const float4*>(
            in + ((size_t)(t * BN + bn)) * 1024 + 512 + d0);
        uint32_t pk[4];
        uint32_t mbits = 0;
        int cnt = 0;
#pragma unroll
        for (int q = 0; q < 4; ++q) {
            float4 x = xp[q];
            float xv[4] = {x.x, x.y, x.z, x.w};
            uint32_t b = 0;
#pragma unroll
            for (int j = 0; j < 4; ++j) {
                int jj = q * 4 + j;
                v[jj] = v[jj] * 0.5f + xv[j];      // *0.5 exact -> bit-identical to ref
                int s = (v[jj] >= 1.0f) ? 1 : 0;
                v[jj] = s ? 0.f : v[jj];
                b |= (uint32_t)s << (8 * j);
                mbits |= (uint32_t)s << jj;
                cnt += s;
            }
            pk[q] = b;
        }
        *reinterpret_cast<uint4*>(g_S + ((size_t)(t * BN + bn)) * 512 + d0) =
            make_uint4(pk[0], pk[1], pk[2], pk[3]);
        // pack pairs of lanes into uint32 (bit k of word w <-> d = 32*w + k)
        uint32_t hi = __shfl_down_sync(0xFFFFFFFF, mbits, 1);
        if ((lane & 1) == 0)
            g_M32[((size_t)(t * BN + bn)) * 16 + (lane >> 1)] = mbits | (hi << 16);
#pragma unroll
        for (int off = 16; off; off >>= 1)
            cnt += __shfl_xor_sync(0xFFFFFFFF, cnt, off);
        if (lane == 0) g_na[t * BN + bn] = cnt;
    }
}

// ---------------- asm helpers ----------------
__device__ __forceinline__ uint32_t smem_u32(const void* p) {
    uint32_t r;
    asm("{ .reg .u64 t; cvta.to.shared.u64 t, %1; cvt.u32.u64 %0, t; }" : "=r"(r) : "l"(p));
    return r;
}
__device__ __forceinline__ void cp16(uint32_t saddr, const void* g) {
    asm volatile("cp.async.cg.shared.global [%0], [%1], 16;" :: "r"(saddr), "l"(g) : "memory");
}
__device__ __forceinline__ void cp8(uint32_t saddr, const void* g) {
    asm volatile("cp.async.ca.shared.global [%0], [%1], 8;" :: "r"(saddr), "l"(g) : "memory");
}
#define CP_COMMIT() asm volatile("cp.async.commit_group;" ::: "memory")
#define CP_WAIT(n)  asm volatile("cp.async.wait_group %0;" :: "n"(n) : "memory")

__device__ __forceinline__ void ldm_x4(uint32_t* a, uint32_t addr) {
    asm volatile("ldmatrix.sync.aligned.m8n8.x4.shared.b16 {%0,%1,%2,%3}, [%4];"
                 : "=r"(a[0]), "=r"(a[1]), "=r"(a[2]), "=r"(a[3]) : "r"(addr));
}
__device__ __forceinline__ void mma_s8(int* c, const uint32_t* a, uint32_t b0, uint32_t b1) {
    asm volatile(
        "mma.sync.aligned.m16n8k32.row.col.s32.s8.s8.s32 "
        "{%0,%1,%2,%3}, {%4,%5,%6,%7}, {%8,%9}, {%0,%1,%2,%3};"
        : "+r"(c[0]), "+r"(c[1]), "+r"(c[2]), "+r"(c[3])
        : "r"(a[0]), "r"(a[1]), "r"(a[2]), "r"(a[3]), "r"(b0), "r"(b1));
}

// ---------------- K2: 2-limb exact GEMM + LIF2 + gated multiply + tie flagging ----------------
// CTA tile 128(bn) x 32(e), 256 threads, 2 CTAs/SM; K_CHUNK=128.
// In-tile pitch padded to 34 floats (bank-conflict-free-ish); outputs staged in smem.
#define M_TILE   128
#define N_TILE   32
#define K_CHUNK  128
#define IN_PITCH 34
#define B_LIMB_B (N_TILE * DIMN)              // 16384 per limb
#define B_BYTES  (2 * B_LIMB_B)               // 32768 (resident W limbs)
#define A_STAGE  (M_TILE * K_CHUNK)           // 16384
#define IN_OFF   (B_BYTES + 2 * A_STAGE)      // 65536: in/out-stage [128 x 34] f32 (17408B)
#define NA_OFF   (IN_OFF + M_TILE * IN_PITCH * 4)   // 82944: na[128]
#define OVF_OFF  (NA_OFF + 512)                      // 83456: ovf[32]
#define SMEM_TOTAL (OVF_OFF + 128)                   // 83584

__device__ __forceinline__ void load_A(uint32_t sA, const signed char* __restrict__ gA, int tid) {
#pragma unroll
    for (int i = 0; i < 4; ++i) {
        int lin = tid + i * 256;             // 1024 x 16B = 16KB
        int row = lin >> 3, ch = lin & 7;
        cp16(sA + (uint32_t)(row * 128 + ((ch ^ (row & 7)) * 16)),
             gA + (size_t)row * 512 + ch * 16);
    }
}

__global__ __launch_bounds__(256, 2)
void k_gemm_lif2(const float* __restrict__ in, const float* __restrict__ bvec,
                 float* __restrict__ out) {
    extern __shared__ char smem[];
    const uint32_t sB = smem_u32(smem);
    const uint32_t sAb = sB + B_BYTES;
    const int tid = threadIdx.x, wid = tid >> 5, lane = tid & 31;
    const int wm = wid & 3, wn = wid >> 2;     // wn in {0,1}
    const int bn0 = blockIdx.x * M_TILE;
    const int et0 = blockIdx.y * N_TILE;

    // ---- resident B: 2 limbs x [32 e-rows x 512 k-bytes], swizzled ----
#pragma unroll
    for (int i = 0; i < 8; ++i) {
        int lin = tid + i * 256;
        int limb = lin >> 10, rem = lin & 1023;
        int n = rem >> 5, kc = rem & 31;
        cp16(sB + (uint32_t)(limb * B_LIMB_B + n * 512 + ((kc ^ (n & 7)) * 16)),
             g_Wl + (size_t)limb * (DIMN * DIMN) + (size_t)(et0 + n) * 512 + kc * 16);
    }
    CP_COMMIT();

    // prologue: A chunks 0,1 (t=0)
    load_A(sAb,           g_S + ((size_t)bn0) * 512 + 0 * K_CHUNK, tid);
    CP_COMMIT();
    load_A(sAb + A_STAGE, g_S + ((size_t)bn0) * 512 + 1 * K_CHUNK, tid);
    CP_COMMIT();

    float bb[2][2];
#pragma unroll
    for (int ng = 0; ng < 2; ++ng)
#pragma unroll
        for (int q = 0; q < 2; ++q)
            bb[ng][q] = bvec[et0 + wn * 16 + ng * 8 + 2 * (lane & 3) + q];

    const int lrow = lane & 15, lch = lane >> 4;
    float*      stg  = (float*)(smem + IN_OFF);
    const int*  naS  = (const int*)(smem + NA_OFF);
    const int*  ovfS = (const int*)(smem + OVF_OFF);

    float v[2][2][4];
#pragma unroll
    for (int i = 0; i < 2; ++i)
#pragma unroll
        for (int ng = 0; ng < 2; ++ng)
#pragma unroll
            for (int e = 0; e < 4; ++e) v[i][ng][e] = 0.f;

    unsigned fl = 0;

#pragma unroll 1
    for (int t = 0; t < T_STEPS; ++t) {
        int acc[2][2][2][4];
#pragma unroll
        for (int l = 0; l < 2; ++l)
#pragma unroll
            for (int i = 0; i < 2; ++i)
#pragma unroll
                for (int ng = 0; ng < 2; ++ng)
#pragma unroll
                    for (int e = 0; e < 4; ++e) acc[l][i][ng][e] = 0;

#pragma unroll 1
        for (int c = 0; c < 4; ++c) {
            const int gc = t * 4 + c;
            CP_WAIT(1);
            __syncthreads();
            const uint32_t sA = sAb + (uint32_t)((gc & 1) * A_STAGE);

#pragma unroll
            for (int ks = 0; ks < 4; ++ks) {
                uint32_t a[2][4];
#pragma unroll
                for (int i = 0; i < 2; ++i) {
                    int row = wm * 32 + i * 16 + lrow;
                    int ch = ks * 2 + lch;
                    ldm_x4(a[i], sA + (uint32_t)(row * 128 + ((ch ^ (row & 7)) * 16)));
                }
#pragma unroll
                for (int l = 0; l < 2; ++l) {
                    uint32_t bf[4];
                    int n = wn * 16 + lrow;
                    int kc = c * 8 + ks * 2 + lch;
                    ldm_x4(bf, sB + (uint32_t)(l * B_LIMB_B + n * 512 + ((kc ^ (n & 7)) * 16)));
#pragma unroll
                    for (int i = 0; i < 2; ++i) {
                        mma_s8(acc[l][i][0], a[i], bf[0], bf[2]);
                        mma_s8(acc[l][i][1], a[i], bf[1], bf[3]);
                    }
                }
            }
            __syncthreads();

            if (c == 0) {
                // prefetch this t's outputs-tile (padded pitch) + na row + ovf bits
                const float* gin = in + ((size_t)(t * BN + bn0)) * 1024 + et0;
#pragma unroll
                for (int i2 = 0; i2 < 8; ++i2) {
                    int lin = i2 * 256 + tid;       // 2048 float2 chunks
                    int r = lin >> 4, c2 = lin & 15;
                    cp8(sB + (uint32_t)(IN_OFF + r * (IN_PITCH * 4) + c2 * 8),
                        gin + (size_t)r * 1024 + c2 * 2);
                }
                if (tid < 32)
                    cp16(sB + (uint32_t)(NA_OFF + tid * 16), g_na + t * BN + bn0 + tid * 4);
                else if (tid < 40)
                    cp16(sB + (uint32_t)(OVF_OFF + (tid - 32) * 16), g_ovf + et0 + (tid - 32) * 4);
            }
            int next = gc + 2;
            if (next < 16) {
                int tn = next >> 2, cn = next & 3;
                load_A(sAb + (uint32_t)((gc & 1) * A_STAGE),
                       g_S + ((size_t)(tn * BN + bn0)) * 512 + cn * K_CHUNK, tid);
            }
            CP_COMMIT();
        }

        // ---- epilogue: exact reconstruction + bias + LIF2 + flag; stage gated outputs ----
#pragma unroll
        for (int i = 0; i < 2; ++i) {
#pragma unroll
            for (int h = 0; h < 2; ++h) {
                int rowl = wm * 32 + i * 16 + (lane >> 2) + h * 8;
                // hard bound on |v - v_ref|: quant (na*2^-18 half-ulp, x2 membrane) + chain
                float na = (float)naS[rowl];
                float tau = fmaf(na, 7.62939453125e-06f, 4e-4f);
#pragma unroll
                for (int ng = 0; ng < 2; ++ng) {
                    int coll = wn * 16 + ng * 8 + 2 * (lane & 3);
                    float s[2];
#pragma unroll
                    for (int q = 0; q < 2; ++q) {
                        int e = 2 * h + q;
                        int lo = acc[0][i][ng][e] + (acc[1][i][ng][e] << 8);  // |.| < 2^24
                        float y = (float)lo * 7.62939453125e-06f;             // * 2^-17, exact
                        float g = y + bb[ng][q];
                        float vv = v[i][ng][e] * 0.5f + g;
                        float sp = (vv >= 1.0f) ? 1.0f : 0.0f;
                        v[i][ng][e] = vv * (1.0f - sp);
                        s[q] = sp;
                        if (fabsf(vv - 1.0f) < tau || ovfS[coll + q])
                            fl |= 1u << (i * 8 + ng * 4 + h * 2 + q);
                    }
                    float* sl = stg + rowl * IN_PITCH + coll;
                    const float2 o = *reinterpret_cast<const float2*>(sl);
                    float2 r;
                    r.x = o.x * s[0];
                    r.y = o.y * s[1];
                    *reinterpret_cast<float2*>(sl) = r;   // same-thread slot: no hazard
                }
            }
        }
        __syncthreads();
        // ---- coalesced copy-out of the staged tile ----
#pragma unroll
        for (int it = 0; it < 8; ++it) {
            int lin = it * 256 + tid;
            int r = lin >> 4, c2 = lin & 15;
            float2 val = *reinterpret_cast<const float2*>(stg + r * IN_PITCH + c2 * 2);
            size_t grow = (size_t)(t * BN) + bn0 + r;
            *reinterpret_cast<float2*>(out + grow * 512 + et0 + c2 * 2) = val;
        }
        // next iteration's c=0 wait+syncthreads orders the stage-buffer reuse
    }

    if (fl) {
#pragma unroll
        for (int i = 0; i < 2; ++i)
#pragma unroll
            for (int ng = 0; ng < 2; ++ng)
#pragma unroll
                for (int h = 0; h < 2; ++h)
#pragma unroll
                    for (int q = 0; q < 2; ++q)
                        if (fl & (1u << (i * 8 + ng * 4 + h * 2 + q))) {
                            int row = bn0 + wm * 32 + i * 16 + (lane >> 2) + h * 8;
                            int col = et0 + wn * 16 + ng * 8 + 2 * (lane & 3) + q;
                            int idx = atomicAdd(&g_nflag, 1);
                            if (idx < FLAG_CAP)
                                g_flags[idx] = (uint32_t)(row * 512 + col);
                        }
    }
}

// ---------------- K3: thread-per-flag fixup (packed masks, spill-free) ----------------
// Per 128-d group: 4 uint4 mask loads + 32 float4 W loads (L2-hot, 1MB total).
// Four exact ascending-d predicated add-chains (one per t) -> bit-identical to reference.
__global__ __launch_bounds__(256)
void k_fixup(const float* __restrict__ in, const float* __restrict__ W,
             const float* __restrict__ bvec, float* __restrict__ out) {
    int n = g_nflag;
    if (n > FLAG_CAP) n = FLAG_CAP;
    for (int idx = blockIdx.x * blockDim.x + threadIdx.x; idx < n;
         idx += gridDim.x * blockDim.x) {
        uint32_t key = g_flags[idx];
        int bn = (int)(key >> 9), e = (int)(key & 511);
        const float4* w4 = reinterpret_cast<const float4*>(W + (size_t)e * 512);

        float acc0 = 0.f, acc1 = 0.f, acc2 = 0.f, acc3 = 0.f;
#pragma unroll 1
        for (int g = 0; g < 4; ++g) {             // 128 d per group
            uint4 m0 = reinterpret_cast<const uint4*>(g_M32 + ((size_t)(0 * BN + bn)) * 16)[g];
            uint4 m1 = reinterpret_cast<const uint4*>(g_M32 + ((size_t)(1 * BN + bn)) * 16)[g];
            uint4 m2 = reinterpret_cast<const uint4*>(g_M32 + ((size_t)(2 * BN + bn)) * 16)[g];
            uint4 m3 = reinterpret_cast<const uint4*>(g_M32 + ((size_t)(3 * BN + bn)) * 16)[g];
#pragma unroll
            for (int u = 0; u < 4; ++u) {         // 32 d per mask word
                uint32_t w0 = (&m0.x)[u], w1 = (&m1.x)[u];
                uint32_t w2 = (&m2.x)[u], w3 = (&m3.x)[u];
#pragma unroll
                for (int b = 0; b < 8; ++b) {     // 4 d per float4
                    float4 wv = w4[g * 32 + u * 8 + b];
                    const float wf[4] = {wv.x, wv.y, wv.z, wv.w};
#pragma unroll
                    for (int j = 0; j < 4; ++j) {
                        int bit = b * 4 + j;
                        acc0 = ((w0 >> bit) & 1u) ? (acc0 + wf[j]) : acc0;
                        acc1 = ((w1 >> bit) & 1u) ? (acc1 + wf[j]) : acc1;
                        acc2 = ((w2 >> bit) & 1u) ? (acc2 + wf[j]) : acc2;
                        acc3 = ((w3 >> bit) & 1u) ? (acc3 + wf[j]) : acc3;
                    }
                }
            }
        }

        float accs[T_STEPS] = {acc0, acc1, acc2, acc3};
        float bias = bvec[e];
        float v = 0.f;
#pragma unroll
        for (int t = 0; t < T_STEPS; ++t) {
            float g = accs[t] + bias;
            float vv = v * 0.5f + g;
            float s = (vv >= 1.0f) ? 1.0f : 0.0f;
            v = vv * (1.0f - s);
            size_t grow = (size_t)(t * BN) + bn;
            out[grow * 512 + e] = in[grow * 1024 + e] * s;
        }
    }
}

// ---------------- launcher ----------------
extern "C" void kernel_launch(void* const* d_in, const int* in_sizes, int n_in,
                              void* d_out, int out_size) {
    const float* inputs = (const float*)d_in[0];   // [4,32,512,1024]
    const float* W      = (const float*)d_in[1];   // [512,512]
    const float* b      = (const float*)d_in[2];   // [512]
    float* out          = (float*)d_out;           // [4,32,512,512]

    cudaFuncSetAttribute(k_gemm_lif2, cudaFuncAttributeMaxDynamicSharedMemorySize, SMEM_TOTAL);

    k_prep<<<LIF1_BLOCKS + SPLIT_BLOCKS, 256>>>(inputs, W);
    k_gemm_lif2<<<dim3(BN / M_TILE, DIMN / N_TILE), 256, SMEM_TOTAL>>>(inputs, b, out);
    k_fixup<<<2048, 256>>>(inputs, W, b, out);
}

// round 17
// speedup vs baseline: 1.6528x; 1.0213x over previous
#include <cuda_runtime.h>
#include <cuda_bf16.h>
#include <cstdint>

#define T_STEPS 4
#define BN      16384            // B*N = 32*512
#define DIMN    512
#define FLAG_CAP (1 << 22)

// ---------------- scratch (device globals; no allocs allowed) ----------------
__device__ __align__(16) signed char g_S[(size_t)T_STEPS * BN * DIMN];  // spikes s8 (32MB)
__device__ __align__(16) uint32_t    g_M32[(size_t)T_STEPS * BN * 16];  // packed spike masks (4MB)
__device__ __align__(16) signed char g_Wl[2 * DIMN * DIMN];             // 2 base-256 limbs of W*2^17
__device__ __align__(16) int g_na[T_STEPS * BN];                        // active count per (t,row)
__device__ __align__(16) int g_ovf[DIMN];                               // per-column quant overflow
__device__ int g_nflag;
__device__ uint32_t g_flags[FLAG_CAP];

// ---------------- K1: LIF1 (bit-exact) + packed masks + counts + W limb split ----------------
#define LIF1_BLOCKS  (BN * 32 / 256)          // 2048
#define SPLIT_BLOCKS ((DIMN * DIMN) / 256)    // 1024

__global__ void k_prep(const float* __restrict__ in, const float* __restrict__ W) {
    int bid = blockIdx.x, tid = threadIdx.x;
    if (bid >= LIF1_BLOCKS) {
        int i = (bid - LIF1_BLOCKS) * 256 + tid;
        if (i == 0) g_nflag = 0;
        int v = (int)llrintf(W[i] * 131072.0f);   // 2^17; |W|<0.249 -> |v| <= 32639
        if (v > 32639)  { v = 32639;  g_ovf[i >> 9] = 1; }
        if (v < -32639) { v = -32639; g_ovf[i >> 9] = 1; }
        int d0 = ((v + 128) & 255) - 128;
        int d1 = (v - d0) >> 8;                   // exact, |d1| <= 127
        g_Wl[i]               = (signed char)d0;
        g_Wl[DIMN * DIMN + i] = (signed char)d1;
        return;
    }
    int gt = bid * 256 + tid;
    int bn = gt >> 5, lane = gt & 31;
    int d0 = lane * 16;
    float v[16];
#pragma unroll
    for (int j = 0; j < 16; ++j) v[j] = 0.f;
#pragma unroll
    for (int t = 0; t < T_STEPS; ++t) {
        const float4* xp = reinterpret_cast<const float4*>(
            in + ((size_t)(t * BN + bn)) * 1024 + 512 + d0);
        uint32_t pk[4];
        uint32_t mbits = 0;
        int cnt = 0;
#pragma unroll
        for (int q = 0; q < 4; ++q) {
            float4 x = xp[q];
            float xv[4] = {x.x, x.y, x.z, x.w};
            uint32_t b = 0;
#pragma unroll
            for (int j = 0; j < 4; ++j) {
                int jj = q * 4 + j;
                v[jj] = v[jj] * 0.5f + xv[j];      // *0.5 exact -> bit-identical to ref
                int s = (v[jj] >= 1.0f) ? 1 : 0;
                v[jj] = s ? 0.f : v[jj];
                b |= (uint32_t)s << (8 * j);
                mbits |= (uint32_t)s << jj;
                cnt += s;
            }
            pk[q] = b;
        }
        *reinterpret_cast<uint4*>(g_S + ((size_t)(t * BN + bn)) * 512 + d0) =
            make_uint4(pk[0], pk[1], pk[2], pk[3]);
        uint32_t hi = __shfl_down_sync(0xFFFFFFFF, mbits, 1);
        if ((lane & 1) == 0)
            g_M32[((size_t)(t * BN + bn)) * 16 + (lane >> 1)] = mbits | (hi << 16);
#pragma unroll
        for (int off = 16; off; off >>= 1)
            cnt += __shfl_xor_sync(0xFFFFFFFF, cnt, off);
        if (lane == 0) g_na[t * BN + bn] = cnt;
    }
}

// ---------------- asm helpers ----------------
__device__ __forceinline__ uint32_t smem_u32(const void* p) {
    uint32_t r;
    asm("{ .reg .u64 t; cvta.to.shared.u64 t, %1; cvt.u32.u64 %0, t; }" : "=r"(r) : "l"(p));
    return r;
}
__device__ __forceinline__ void cp16(uint32_t saddr, const void* g) {
    asm volatile("cp.async.cg.shared.global [%0], [%1], 16;" :: "r"(saddr), "l"(g) : "memory");
}
__device__ __forceinline__ void cp8(uint32_t saddr, const void* g) {
    asm volatile("cp.async.ca.shared.global [%0], [%1], 8;" :: "r"(saddr), "l"(g) : "memory");
}
#define CP_COMMIT() asm volatile("cp.async.commit_group;" ::: "memory")
#define CP_WAIT(n)  asm volatile("cp.async.wait_group %0;" :: "n"(n) : "memory")

__device__ __forceinline__ void ldm_x4(uint32_t* a, uint32_t addr) {
    asm volatile("ldmatrix.sync.aligned.m8n8.x4.shared.b16 {%0,%1,%2,%3}, [%4];"
                 : "=r"(a[0]), "=r"(a[1]), "=r"(a[2]), "=r"(a[3]) : "r"(addr));
}
__device__ __forceinline__ void mma_s8(int* c, const uint32_t* a, uint32_t b0, uint32_t b1) {
    asm volatile(
        "mma.sync.aligned.m16n8k32.row.col.s32.s8.s8.s32 "
        "{%0,%1,%2,%3}, {%4,%5,%6,%7}, {%8,%9}, {%0,%1,%2,%3};"
        : "+r"(c[0]), "+r"(c[1]), "+r"(c[2]), "+r"(c[3])
        : "r"(a[0]), "r"(a[1]), "r"(a[2]), "r"(a[3]), "r"(b0), "r"(b1));
}
__device__ __forceinline__ int dp4a_s8(uint32_t a, uint32_t b, int c) {
    int r;
    asm("dp4a.s32.s32 %0, %1, %2, %3;" : "=r"(r) : "r"(a), "r"(b), "r"(c));
    return r;
}

// ---------------- K2: hybrid tensor+dp4a exact GEMM + LIF2 + flagging ----------------
// CTA tile 128(bn) x 32(e), 256 threads, 2 CTAs/SM; K_CHUNK=128.
// Per chunk: k32-steps 0..2 on the tensor pipe (MMA), step 3 on the SIMT pipe (dp4a).
#define M_TILE   128
#define N_TILE   32
#define K_CHUNK  128
#define IN_PITCH 34
#define B_LIMB_B (N_TILE * DIMN)              // 16384 per limb
#define B_BYTES  (2 * B_LIMB_B)               // 32768 (resident W limbs)
#define A_STAGE  (M_TILE * K_CHUNK)           // 16384
#define IN_OFF   (B_BYTES + 2 * A_STAGE)      // 65536: in/out-stage [128 x 34] f32
#define NA_OFF   (IN_OFF + M_TILE * IN_PITCH * 4)   // 82944: na[128]
#define OVF_OFF  (NA_OFF + 512)                      // 83456: ovf[32]
#define SMEM_TOTAL (OVF_OFF + 128)                   // 83584

__device__ __forceinline__ void load_A(uint32_t sA, const signed char* __restrict__ gA, int tid) {
#pragma unroll
    for (int i = 0; i < 4; ++i) {
        int lin = tid + i * 256;             // 1024 x 16B = 16KB
        int row = lin >> 3, ch = lin & 7;
        cp16(sA + (uint32_t)(row * 128 + ((ch ^ (row & 7)) * 16)),
             gA + (size_t)row * 512 + ch * 16);
    }
}

__global__ __launch_bounds__(256, 2)
void k_gemm_lif2(const float* __restrict__ in, const float* __restrict__ bvec,
                 float* __restrict__ out) {
    extern __shared__ char smem[];
    const uint32_t sB = smem_u32(smem);
    const uint32_t sAb = sB + B_BYTES;
    const int tid = threadIdx.x, wid = tid >> 5, lane = tid & 31;
    const int wm = wid & 3, wn = wid >> 2;     // wn in {0,1}
    const int bn0 = blockIdx.x * M_TILE;
    const int et0 = blockIdx.y * N_TILE;

    // ---- resident B: 2 limbs x [32 e-rows x 512 k-bytes], swizzled ----
#pragma unroll
    for (int i = 0; i < 8; ++i) {
        int lin = tid + i * 256;
        int limb = lin >> 10, rem = lin & 1023;
        int n = rem >> 5, kc = rem & 31;
        cp16(sB + (uint32_t)(limb * B_LIMB_B + n * 512 + ((kc ^ (n & 7)) * 16)),
             g_Wl + (size_t)limb * (DIMN * DIMN) + (size_t)(et0 + n) * 512 + kc * 16);
    }
    CP_COMMIT();

    load_A(sAb,           g_S + ((size_t)bn0) * 512 + 0 * K_CHUNK, tid);
    CP_COMMIT();
    load_A(sAb + A_STAGE, g_S + ((size_t)bn0) * 512 + 1 * K_CHUNK, tid);
    CP_COMMIT();

    float bb[2][2];
#pragma unroll
    for (int ng = 0; ng < 2; ++ng)
#pragma unroll
        for (int q = 0; q < 2; ++q)
            bb[ng][q] = bvec[et0 + wn * 16 + ng * 8 + 2 * (lane & 3) + q];

    const int lrow = lane & 15, lch = lane >> 4;
    float*      stg  = (float*)(smem + IN_OFF);
    const int*  naS  = (const int*)(smem + NA_OFF);
    const int*  ovfS = (const int*)(smem + OVF_OFF);

    float v[2][2][4];
#pragma unroll
    for (int i = 0; i < 2; ++i)
#pragma unroll
        for (int ng = 0; ng < 2; ++ng)
#pragma unroll
            for (int e = 0; e < 4; ++e) v[i][ng][e] = 0.f;

    unsigned fl = 0;

#pragma unroll 1
    for (int t = 0; t < T_STEPS; ++t) {
        int acc[2][2][2][4];
#pragma unroll
        for (int l = 0; l < 2; ++l)
#pragma unroll
            for (int i = 0; i < 2; ++i)
#pragma unroll
                for (int ng = 0; ng < 2; ++ng)
#pragma unroll
                    for (int e = 0; e < 4; ++e) acc[l][i][ng][e] = 0;

#pragma unroll 1
        for (int c = 0; c < 4; ++c) {
            const int gc = t * 4 + c;
            CP_WAIT(1);
            __syncthreads();
            const uint32_t sA = sAb + (uint32_t)((gc & 1) * A_STAGE);
            const char* pA = smem + B_BYTES + (gc & 1) * A_STAGE;

            // ---- tensor path: k32-steps 0..2 ----
#pragma unroll
            for (int ks = 0; ks < 3; ++ks) {
                uint32_t a[2][4];
#pragma unroll
                for (int i = 0; i < 2; ++i) {
                    int row = wm * 32 + i * 16 + lrow;
                    int ch = ks * 2 + lch;
                    ldm_x4(a[i], sA + (uint32_t)(row * 128 + ((ch ^ (row & 7)) * 16)));
                }
#pragma unroll
                for (int l = 0; l < 2; ++l) {
                    uint32_t bf[4];
                    int n = wn * 16 + lrow;
                    int kc = c * 8 + ks * 2 + lch;
                    ldm_x4(bf, sB + (uint32_t)(l * B_LIMB_B + n * 512 + ((kc ^ (n & 7)) * 16)));
#pragma unroll
                    for (int i = 0; i < 2; ++i) {
                        mma_s8(acc[l][i][0], a[i], bf[0], bf[2]);
                        mma_s8(acc[l][i][1], a[i], bf[1], bf[3]);
                    }
                }
            }

            // ---- dp4a path: k32-step 3 (bytes 96..127) on the SIMT pipe; exact ----
#pragma unroll
            for (int ksub = 0; ksub < 2; ++ksub) {
                const int ch = 6 + ksub;
                uint32_t Aw[4][4];
#pragma unroll
                for (int rr = 0; rr < 4; ++rr) {
                    int r = wm * 32 + (rr >> 1) * 16 + (lane >> 2) + (rr & 1) * 8;
                    uint4 av = *reinterpret_cast<const uint4*>(
                        pA + r * 128 + ((ch ^ (r & 7)) * 16));
                    Aw[rr][0] = av.x; Aw[rr][1] = av.y; Aw[rr][2] = av.z; Aw[rr][3] = av.w;
                }
#pragma unroll
                for (int l = 0; l < 2; ++l) {
#pragma unroll
                    for (int cc = 0; cc < 4; ++cc) {
                        int ng = cc >> 1, q = cc & 1;
                        int n = wn * 16 + ng * 8 + 2 * (lane & 3) + q;
                        int kc = c * 8 + 6 + ksub;
                        uint4 bv = *reinterpret_cast<const uint4*>(
                            smem + l * B_LIMB_B + n * 512 + ((kc ^ (n & 7)) * 16));
                        uint32_t bw[4] = {bv.x, bv.y, bv.z, bv.w};
#pragma unroll
                        for (int rr = 0; rr < 4; ++rr) {
                            int i = rr >> 1, e = (rr & 1) * 2 + q;
#pragma unroll
                            for (int w = 0; w < 4; ++w)
                                acc[l][i][ng][e] = dp4a_s8(Aw[rr][w], bw[w], acc[l][i][ng][e]);
                        }
                    }
                }
            }
            __syncthreads();

            if (c == 0) {
                const float* gin = in + ((size_t)(t * BN + bn0)) * 1024 + et0;
#pragma unroll
                for (int i2 = 0; i2 < 8; ++i2) {
                    int lin = i2 * 256 + tid;
                    int r = lin >> 4, c2 = lin & 15;
                    cp8(sB + (uint32_t)(IN_OFF + r * (IN_PITCH * 4) + c2 * 8),
                        gin + (size_t)r * 1024 + c2 * 2);
                }
                if (tid < 32)
                    cp16(sB + (uint32_t)(NA_OFF + tid * 16), g_na + t * BN + bn0 + tid * 4);
                else if (tid < 40)
                    cp16(sB + (uint32_t)(OVF_OFF + (tid - 32) * 16), g_ovf + et0 + (tid - 32) * 4);
            }
            int next = gc + 2;
            if (next < 16) {
                int tn = next >> 2, cn = next & 3;
                load_A(sAb + (uint32_t)((gc & 1) * A_STAGE),
                       g_S + ((size_t)(tn * BN + bn0)) * 512 + cn * K_CHUNK, tid);
            }
            CP_COMMIT();
        }

        // ---- epilogue: exact reconstruction + bias + LIF2 + flag; stage gated outputs ----
#pragma unroll
        for (int i = 0; i < 2; ++i) {
#pragma unroll
            for (int h = 0; h < 2; ++h) {
                int rowl = wm * 32 + i * 16 + (lane >> 2) + h * 8;
                float na = (float)naS[rowl];
                float tau = fmaf(na, 7.62939453125e-06f, 4e-4f);
#pragma unroll
                for (int ng = 0; ng < 2; ++ng) {
                    int coll = wn * 16 + ng * 8 + 2 * (lane & 3);
                    float s[2];
#pragma unroll
                    for (int q = 0; q < 2; ++q) {
                        int e = 2 * h + q;
                        int lo = acc[0][i][ng][e] + (acc[1][i][ng][e] << 8);  // |.| < 2^24
                        float y = (float)lo * 7.62939453125e-06f;             // * 2^-17, exact
                        float g = y + bb[ng][q];
                        float vv = v[i][ng][e] * 0.5f + g;
                        float sp = (vv >= 1.0f) ? 1.0f : 0.0f;
                        v[i][ng][e] = vv * (1.0f - sp);
                        s[q] = sp;
                        if (fabsf(vv - 1.0f) < tau || ovfS[coll + q])
                            fl |= 1u << (i * 8 + ng * 4 + h * 2 + q);
                    }
                    float* sl = stg + rowl * IN_PITCH + coll;
                    const float2 o = *reinterpret_cast<const float2*>(sl);
                    float2 r;
                    r.x = o.x * s[0];
                    r.y = o.y * s[1];
                    *reinterpret_cast<float2*>(sl) = r;
                }
            }
        }
        __syncthreads();
#pragma unroll
        for (int it = 0; it < 8; ++it) {
            int lin = it * 256 + tid;
            int r = lin >> 4, c2 = lin & 15;
            float2 val = *reinterpret_cast<const float2*>(stg + r * IN_PITCH + c2 * 2);
            size_t grow = (size_t)(t * BN) + bn0 + r;
            *reinterpret_cast<float2*>(out + grow * 512 + et0 + c2 * 2) = val;
        }
    }

    if (fl) {
#pragma unroll
        for (int i = 0; i < 2; ++i)
#pragma unroll
            for (int ng = 0; ng < 2; ++ng)
#pragma unroll
                for (int h = 0; h < 2; ++h)
#pragma unroll
                    for (int q = 0; q < 2; ++q)
                        if (fl & (1u << (i * 8 + ng * 4 + h * 2 + q))) {
                            int row = bn0 + wm * 32 + i * 16 + (lane >> 2) + h * 8;
                            int col = et0 + wn * 16 + ng * 8 + 2 * (lane & 3) + q;
                            int idx = atomicAdd(&g_nflag, 1);
                            if (idx < FLAG_CAP)
                                g_flags[idx] = (uint32_t)(row * 512 + col);
                        }
    }
}

// ---------------- K3: thread-per-flag fixup (packed masks, spill-free) ----------------
__global__ __launch_bounds__(256)
void k_fixup(const float* __restrict__ in, const float* __restrict__ W,
             const float* __restrict__ bvec, float* __restrict__ out) {
    int n = g_nflag;
    if (n > FLAG_CAP) n = FLAG_CAP;
    for (int idx = blockIdx.x * blockDim.x + threadIdx.x; idx < n;
         idx += gridDim.x * blockDim.x) {
        uint32_t key = g_flags[idx];
        int bn = (int)(key >> 9), e = (int)(key & 511);
        const float4* w4 = reinterpret_cast<const float4*>(W + (size_t)e * 512);

        float acc0 = 0.f, acc1 = 0.f, acc2 = 0.f, acc3 = 0.f;
#pragma unroll 1
        for (int g = 0; g < 4; ++g) {             // 128 d per group
            uint4 m0 = reinterpret_cast<const uint4*>(g_M32 + ((size_t)(0 * BN + bn)) * 16)[g];
            uint4 m1 = reinterpret_cast<const uint4*>(g_M32 + ((size_t)(1 * BN + bn)) * 16)[g];
            uint4 m2 = reinterpret_cast<const uint4*>(g_M32 + ((size_t)(2 * BN + bn)) * 16)[g];
            uint4 m3 = reinterpret_cast<const uint4*>(g_M32 + ((size_t)(3 * BN + bn)) * 16)[g];
#pragma unroll
            for (int u = 0; u < 4; ++u) {
                uint32_t w0 = (&m0.x)[u], w1 = (&m1.x)[u];
                uint32_t w2 = (&m2.x)[u], w3 = (&m3.x)[u];
#pragma unroll
                for (int b = 0; b < 8; ++b) {
                    float4 wv = w4[g * 32 + u * 8 + b];
                    const float wf[4] = {wv.x, wv.y, wv.z, wv.w};
#pragma unroll
                    for (int j = 0; j < 4; ++j) {
                        int bit = b * 4 + j;
                        acc0 = ((w0 >> bit) & 1u) ? (acc0 + wf[j]) : acc0;
                        acc1 = ((w1 >> bit) & 1u) ? (acc1 + wf[j]) : acc1;
                        acc2 = ((w2 >> bit) & 1u) ? (acc2 + wf[j]) : acc2;
                        acc3 = ((w3 >> bit) & 1u) ? (acc3 + wf[j]) : acc3;
                    }
                }
            }
        }

        float accs[T_STEPS] = {acc0, acc1, acc2, acc3};
        float bias = bvec[e];
        float v = 0.f;
#pragma unroll
        for (int t = 0; t < T_STEPS; ++t) {
            float g = accs[t] + bias;
            float vv = v * 0.5f + g;
            float s = (vv >= 1.0f) ? 1.0f : 0.0f;
            v = vv * (1.0f - s);
            size_t grow = (size_t)(t * BN) + bn;
            out[grow * 512 + e] = in[grow * 1024 + e] * s;
        }
    }
}

// ---------------- launcher ----------------
extern "C" void kernel_launch(void* const* d_in, const int* in_sizes, int n_in,
                              void* d_out, int out_size) {
    const float* inputs = (const float*)d_in[0];   // [4,32,512,1024]
    const float* W      = (const float*)d_in[1];   // [512,512]
    const float* b      = (const float*)d_in[2];   // [512]
    float* out          = (float*)d_out;           // [4,32,512,512]

    cudaFuncSetAttribute(k_gemm_lif2, cudaFuncAttributeMaxDynamicSharedMemorySize, SMEM_TOTAL);

    k_prep<<<LIF1_BLOCKS + SPLIT_BLOCKS, 256>>>(inputs, W);
    k_gemm_lif2<<<dim3(BN / M_TILE, DIMN / N_TILE), 256, SMEM_TOTAL>>>(inputs, b, out);
    k_fixup<<<2048, 256>>>(inputs, W, b, out);
}